// round 1
// baseline (speedup 1.0000x reference)
#include <cuda_runtime.h>
#include <cuda_bf16.h>
#include <cstdint>

// Problem constants (fixed shapes from reference setup_inputs)
#define NN   256          // samples
#define CC   3            // channels
#define TT   300          // frames
#define VV   25           // joints
#define MM   2            // persons
#define DD   256          // feature dim
#define KK   5            // n_classes
#define TOPK 64
#define LTOT (NN*MM*TT)   // 153600 rows of x_T
#define EPSV 1e-8f

// -------- scratch (no allocations allowed) --------
__device__ float g_cls_sum[KK * DD];   // per-class feature sums
__device__ float g_cnt[KK];            // per-class counts (float)
__device__ float g_cm[KK * DD];        // class means
__device__ float g_inter[KK];          // inter-class distances
__device__ float g_Sb;                 // sum counts[k]*inter[k]
__device__ float g_Sw;                 // sum of intra
__device__ float g_VF[NN * TT];        // frame scores averaged over M
__device__ int   g_idx[NN * TOPK];     // selected frame indices (sorted)

// -------- kernel 0: zero scratch --------
__global__ void k_zero() {
    int i = blockIdx.x * 256 + threadIdx.x;
    if (i < NN * TT) g_VF[i] = 0.f;
    if (i < KK * DD) g_cls_sum[i] = 0.f;
    if (i < KK)      g_cnt[i] = 0.f;
    if (i == 0)      g_Sw = 0.f;
}

// -------- kernel 1: per-class sums + counts --------
// grid = LTOT/256 blocks, 256 threads. thread = column d, block owns 256 rows.
// label is uniform across the block for a given row -> uniform branch, no divergence.
__global__ void __launch_bounds__(256) k_stats(const float* __restrict__ xT,
                                               const int* __restrict__ labels) {
    __shared__ int   s_lbl[256];
    __shared__ float s_cnt[KK];
    int tid = threadIdx.x;
    int base = blockIdx.x * 256;
    if (tid < KK) s_cnt[tid] = 0.f;
    s_lbl[tid] = labels[base + tid];
    __syncthreads();
    atomicAdd(&s_cnt[s_lbl[tid]], 1.f);

    float a0 = 0.f, a1 = 0.f, a2 = 0.f, a3 = 0.f, a4 = 0.f;
    const float* p = xT + (size_t)base * DD + tid;
#pragma unroll 4
    for (int r = 0; r < 256; r++) {
        float v = __ldg(p + (size_t)r * DD);
        int l = s_lbl[r];
        if      (l == 0) a0 += v;
        else if (l == 1) a1 += v;
        else if (l == 2) a2 += v;
        else if (l == 3) a3 += v;
        else             a4 += v;
    }
    atomicAdd(&g_cls_sum[0 * DD + tid], a0);
    atomicAdd(&g_cls_sum[1 * DD + tid], a1);
    atomicAdd(&g_cls_sum[2 * DD + tid], a2);
    atomicAdd(&g_cls_sum[3 * DD + tid], a3);
    atomicAdd(&g_cls_sum[4 * DD + tid], a4);
    __syncthreads();
    if (tid < KK) atomicAdd(&g_cnt[tid], s_cnt[tid]);
}

// -------- kernel 2: class means, inter distances, Sb (single block, 256 thr) --------
__global__ void __launch_bounds__(256) k_finalize() {
    __shared__ float s_cnt[KK];
    __shared__ float red[256];
    int d = threadIdx.x;
    if (d < KK) s_cnt[d] = g_cnt[d];
    __syncthreads();

    float om = 0.f;
    float cm[KK];
#pragma unroll
    for (int k = 0; k < KK; k++) {
        float s = g_cls_sum[k * DD + d];
        om += s;
        cm[k] = s / fmaxf(s_cnt[k], 1.f);
        g_cm[k * DD + d] = cm[k];
    }
    om *= (1.0f / (float)LTOT);

#pragma unroll
    for (int k = 0; k < KK; k++) {
        float diff = cm[k] - om;
        red[d] = diff * diff;
        __syncthreads();
        for (int s = 128; s > 0; s >>= 1) {
            if (d < s) red[d] += red[d + s];
            __syncthreads();
        }
        if (d == 0) g_inter[k] = red[0];
        __syncthreads();
    }
    if (d == 0) {
        float sb = 0.f;
#pragma unroll
        for (int k = 0; k < KK; k++) sb += s_cnt[k] * g_inter[k];
        g_Sb = sb;
    }
}

// -------- kernel 3: intra per row, frame scores -> VF, Sw --------
// grid = LTOT/256 blocks, 256 threads = 8 warps; each warp handles 32 rows.
__global__ void __launch_bounds__(256) k_intra(const float* __restrict__ xT,
                                               const int* __restrict__ labels) {
    __shared__ float s_cm[KK * DD];
    __shared__ float s_inter[KK];
    __shared__ float s_sw[8];
    int tid = threadIdx.x, lane = tid & 31, w = tid >> 5;
    for (int i = tid; i < KK * DD; i += 256) s_cm[i] = g_cm[i];
    if (tid < KK) s_inter[tid] = g_inter[tid];
    __syncthreads();

    int rowbase = blockIdx.x * 256 + w * 32;
    int mylbl = labels[rowbase + lane];   // coalesced preload of this warp's 32 labels
    float swacc = 0.f;

    for (int rr = 0; rr < 32; rr++) {
        int row = rowbase + rr;
        int lbl = __shfl_sync(0xFFFFFFFFu, mylbl, rr);
        const float* p = xT + (size_t)row * DD;
        const float* m = s_cm + lbl * DD;
        float acc = 0.f;
#pragma unroll
        for (int j = 0; j < 8; j++) {
            float dv = __ldg(p + lane + j * 32) - m[lane + j * 32];
            acc = fmaf(dv, dv, acc);
        }
#pragma unroll
        for (int o = 16; o; o >>= 1) acc += __shfl_xor_sync(0xFFFFFFFFu, acc, o);
        if (lane == 0) {
            swacc += acc;
            float fs = s_inter[lbl] / (acc + EPSV);
            int n = row / (MM * TT);
            int t = row % TT;
            atomicAdd(&g_VF[n * TT + t], fs * (1.0f / (float)MM));
        }
    }
    if (lane == 0) s_sw[w] = swacc;
    __syncthreads();
    if (tid == 0) {
        float s = 0.f;
#pragma unroll
        for (int i = 0; i < 8; i++) s += s_sw[i];
        atomicAdd(&g_Sw, s);
    }
}

// -------- kernel 4: top-64 of 300 per sample (rank counting, jax tie semantics) --------
__global__ void __launch_bounds__(320) k_topk() {
    __shared__ float v[TT];
    __shared__ int   flag[TT];
    int n = blockIdx.x;
    int t = threadIdx.x;
    if (t < TT) v[t] = g_VF[n * TT + t];
    __syncthreads();
    if (t < TT) {
        float mv = v[t];
        int rank = 0;
        for (int j = 0; j < TT; j++) {
            float o = v[j];
            rank += (o > mv) || (o == mv && j < t);
        }
        flag[t] = (rank < TOPK) ? 1 : 0;
    }
    __syncthreads();
    if (t < TT && flag[t]) {
        int pos = 0;
        for (int j = 0; j < t; j++) pos += flag[j];
        g_idx[n * TOPK + pos] = t;
    }
}

// -------- kernel 5: gather x_select + write loss --------
__global__ void __launch_bounds__(256) k_gather(const float* __restrict__ x,
                                                float* __restrict__ out) {
    size_t i = (size_t)blockIdx.x * 256 + threadIdx.x;
    if (i == 0) out[0] = g_Sw / (g_Sb + EPSV);
    const size_t TOTAL = (size_t)NN * CC * TOPK * VV * MM;  // 2,457,600
    if (i < TOTAL) {
        int m = (int)(i % MM);
        int v = (int)((i / MM) % VV);
        int j = (int)((i / (MM * VV)) % TOPK);
        int c = (int)((i / ((size_t)MM * VV * TOPK)) % CC);
        int n = (int)(i / ((size_t)MM * VV * TOPK * CC));
        int t = g_idx[n * TOPK + j];
        size_t src = ((((size_t)n * CC + c) * TT + t) * VV + v) * MM + m;
        out[1 + i] = __ldg(x + src);
    }
}

extern "C" void kernel_launch(void* const* d_in, const int* in_sizes, int n_in,
                              void* d_out, int out_size) {
    const float* x      = (const float*)d_in[0];   // [256,3,300,25,2]
    const float* xT     = (const float*)d_in[1];   // [153600,256]
    const int*   labels = (const int*)d_in[2];     // [153600] int32
    float* out = (float*)d_out;                    // [1 + 2457600]
    (void)in_sizes; (void)n_in; (void)out_size;

    k_zero<<<(NN * TT + 255) / 256, 256>>>();
    k_stats<<<LTOT / 256, 256>>>(xT, labels);
    k_finalize<<<1, 256>>>();
    k_intra<<<LTOT / 256, 256>>>(xT, labels);
    k_topk<<<NN, 320>>>();
    const size_t TOTAL = (size_t)NN * CC * TOPK * VV * MM;
    k_gather<<<(unsigned)((TOTAL + 255) / 256), 256>>>(x, out);
}

// round 3
// speedup vs baseline: 1.3063x; 1.3063x over previous
#include <cuda_runtime.h>
#include <cuda_bf16.h>
#include <cstdint>

#define NN   256
#define CC   3
#define TT   300
#define VV   25
#define MM   2
#define DD   256
#define KK   5
#define TOPK 64
#define LTOT (NN*MM*TT)     // 153600
#define RPS  (MM*TT)        // 600 rows per sample
#define OUTS (CC*TOPK*VV*MM) // 9600 floats per sample
#define EPSV 1e-8f

// -------- scratch --------
__device__ float g_cls_sum[KK * DD];
__device__ float g_cnt[KK];
__device__ float g_cm[KK * DD];
__device__ float g_inter[KK];
__device__ float g_Sb;
__device__ float g_Sw;

// -------- kernel 0: zero (1 block) --------
__global__ void k_zero() {
    int i = threadIdx.x;
    for (int j = i; j < KK * DD; j += 256) g_cls_sum[j] = 0.f;
    if (i < KK) g_cnt[i] = 0.f;
    if (i == 0) g_Sw = 0.f;
}

// -------- kernel 1: per-class sums + counts (vectorized) --------
// 600 blocks x 256 threads. Block owns 256 rows. Thread = (slice s = tid>>6, colgroup c = tid&63).
// Each warp has uniform slice -> uniform label per row -> no divergence.
__global__ void __launch_bounds__(256) k_stats(const float4* __restrict__ xT4,
                                               const int* __restrict__ labels) {
    __shared__ int    s_lbl[256];
    __shared__ float  s_cnt[KK];
    __shared__ float4 s_part[4][KK][64];   // 20 KB
    int tid = threadIdx.x;
    int c = tid & 63;
    int s = tid >> 6;
    int base = blockIdx.x * 256;
    if (tid < KK) s_cnt[tid] = 0.f;
    s_lbl[tid] = labels[base + tid];
    __syncthreads();
    atomicAdd(&s_cnt[s_lbl[tid]], 1.f);

    float4 a[KK];
#pragma unroll
    for (int k = 0; k < KK; k++) a[k] = make_float4(0.f, 0.f, 0.f, 0.f);

    const float4* p = xT4 + (size_t)(base + s) * 64 + c;
#pragma unroll 4
    for (int it = 0; it < 64; it++) {
        float4 v = __ldg(p + (size_t)it * 4 * 64);
        int l = s_lbl[it * 4 + s];
        if      (l == 0) { a[0].x += v.x; a[0].y += v.y; a[0].z += v.z; a[0].w += v.w; }
        else if (l == 1) { a[1].x += v.x; a[1].y += v.y; a[1].z += v.z; a[1].w += v.w; }
        else if (l == 2) { a[2].x += v.x; a[2].y += v.y; a[2].z += v.z; a[2].w += v.w; }
        else if (l == 3) { a[3].x += v.x; a[3].y += v.y; a[3].z += v.z; a[3].w += v.w; }
        else             { a[4].x += v.x; a[4].y += v.y; a[4].z += v.z; a[4].w += v.w; }
    }
#pragma unroll
    for (int k = 0; k < KK; k++) s_part[s][k][c] = a[k];
    __syncthreads();

    for (int idx = tid; idx < KK * 64; idx += 256) {
        int k = idx >> 6, cc = idx & 63;
        float4 s0 = s_part[0][k][cc], s1 = s_part[1][k][cc];
        float4 s2 = s_part[2][k][cc], s3 = s_part[3][k][cc];
        float4 t;
        t.x = (s0.x + s1.x) + (s2.x + s3.x);
        t.y = (s0.y + s1.y) + (s2.y + s3.y);
        t.z = (s0.z + s1.z) + (s2.z + s3.z);
        t.w = (s0.w + s1.w) + (s2.w + s3.w);
        atomicAdd(&g_cls_sum[k * DD + cc * 4 + 0], t.x);
        atomicAdd(&g_cls_sum[k * DD + cc * 4 + 1], t.y);
        atomicAdd(&g_cls_sum[k * DD + cc * 4 + 2], t.z);
        atomicAdd(&g_cls_sum[k * DD + cc * 4 + 3], t.w);
    }
    if (tid < KK) atomicAdd(&g_cnt[tid], s_cnt[tid]);
}

// -------- kernel 2: means, inter, Sb (1 block) --------
__global__ void __launch_bounds__(256) k_finalize() {
    __shared__ float s_cnt[KK];
    __shared__ float red[256];
    int d = threadIdx.x;
    if (d < KK) s_cnt[d] = g_cnt[d];
    __syncthreads();

    float om = 0.f;
    float cm[KK];
#pragma unroll
    for (int k = 0; k < KK; k++) {
        float s = g_cls_sum[k * DD + d];
        om += s;
        cm[k] = s / fmaxf(s_cnt[k], 1.f);
        g_cm[k * DD + d] = cm[k];
    }
    om *= (1.0f / (float)LTOT);

#pragma unroll
    for (int k = 0; k < KK; k++) {
        float diff = cm[k] - om;
        red[d] = diff * diff;
        __syncthreads();
        for (int s = 128; s > 0; s >>= 1) {
            if (d < s) red[d] += red[d + s];
            __syncthreads();
        }
        if (d == 0) g_inter[k] = red[0];
        __syncthreads();
    }
    if (d == 0) {
        float sb = 0.f;
#pragma unroll
        for (int k = 0; k < KK; k++) sb += s_cnt[k] * g_inter[k];
        g_Sb = sb;
    }
}

// -------- kernel 3: fused intra + frame scores + topk + gather --------
// 256 blocks (one per sample), 320 threads = 10 warps; warp handles 60 rows.
__global__ void __launch_bounds__(320) k_fused(const float4* __restrict__ xT4,
                                               const int* __restrict__ labels,
                                               const float* __restrict__ x,
                                               float* __restrict__ out) {
    __shared__ float s_cm[KK * DD];   // 5 KB
    __shared__ float s_inter[KK];
    __shared__ int   s_lbl[RPS];
    __shared__ float s_fs[RPS];
    __shared__ float s_v[TT];
    __shared__ int   s_flag[TT];
    __shared__ int   s_idx[TOPK];
    __shared__ float s_sw[10];

    int n = (NN - 1) - blockIdx.x;   // reversed: tail of xT is L2-hot after k_stats
    int tid = threadIdx.x, lane = tid & 31, w = tid >> 5;

    for (int i = tid; i < KK * DD; i += 320) s_cm[i] = g_cm[i];
    if (tid < KK) s_inter[tid] = g_inter[tid];
    for (int i = tid; i < RPS; i += 320) s_lbl[i] = labels[n * RPS + i];
    __syncthreads();

    const float4* cm4 = (const float4*)s_cm;
    float swacc = 0.f;
    int rbeg = w * 60;
    for (int r = rbeg; r < rbeg + 60; r++) {
        int lbl = s_lbl[r];
        const float4* p = xT4 + (size_t)(n * RPS + r) * 64;
        const float4* m = cm4 + lbl * 64;
        float acc = 0.f;
#pragma unroll
        for (int j = 0; j < 2; j++) {
            float4 xv = __ldg(p + lane + 32 * j);
            float4 mv = m[lane + 32 * j];
            float dx = xv.x - mv.x, dy = xv.y - mv.y;
            float dz = xv.z - mv.z, dw = xv.w - mv.w;
            acc = fmaf(dx, dx, acc); acc = fmaf(dy, dy, acc);
            acc = fmaf(dz, dz, acc); acc = fmaf(dw, dw, acc);
        }
#pragma unroll
        for (int o = 16; o; o >>= 1) acc += __shfl_xor_sync(0xFFFFFFFFu, acc, o);
        if (lane == 0) {
            swacc += acc;
            s_fs[r] = s_inter[lbl] / (acc + EPSV);
        }
    }
    if (lane == 0) s_sw[w] = swacc;
    __syncthreads();
    if (tid == 0) {
        float s = 0.f;
#pragma unroll
        for (int i = 0; i < 10; i++) s += s_sw[i];
        atomicAdd(&g_Sw, s);
    }

    // VF = mean over M
    if (tid < TT) s_v[tid] = 0.5f * (s_fs[tid] + s_fs[TT + tid]);
    __syncthreads();

    // topk via rank counting (jax tie semantics: smaller index wins ties)
    if (tid < TT) {
        float mv = s_v[tid];
        int rank = 0;
        for (int j = 0; j < TT; j++) {
            float o = s_v[j];
            rank += (o > mv) || (o == mv && j < tid);
        }
        s_flag[tid] = (rank < TOPK) ? 1 : 0;
    }
    __syncthreads();
    if (tid < TT && s_flag[tid]) {
        int pos = 0;
        for (int j = 0; j < tid; j++) pos += s_flag[j];
        s_idx[pos] = tid;
    }
    __syncthreads();

    // gather x_select for this sample: out layout [N, C, TOPK, V, M]
    const float* xb = x + (size_t)n * CC * TT * (VV * MM);
    float* ob = out + 1 + (size_t)n * OUTS;
    for (int o = tid; o < OUTS; o += 320) {
        int cj = o / (VV * MM);          // c*64 + j
        int vm = o - cj * (VV * MM);
        int j = cj & 63;
        int c = cj >> 6;
        int t = s_idx[j];
        ob[o] = __ldg(xb + ((size_t)c * TT + t) * (VV * MM) + vm);
    }
}

// -------- kernel 4: loss scalar --------
__global__ void k_loss(float* __restrict__ out) {
    out[0] = g_Sw / (g_Sb + EPSV);
}

extern "C" void kernel_launch(void* const* d_in, const int* in_sizes, int n_in,
                              void* d_out, int out_size) {
    const float*  x      = (const float*)d_in[0];
    const float4* xT4    = (const float4*)d_in[1];
    const int*    labels = (const int*)d_in[2];
    float* out = (float*)d_out;
    (void)in_sizes; (void)n_in; (void)out_size;

    k_zero<<<1, 256>>>();
    k_stats<<<LTOT / 256, 256>>>(xT4, labels);
    k_finalize<<<1, 256>>>();
    k_fused<<<NN, 320>>>(xT4, labels, x, out);
    k_loss<<<1, 1>>>(out);
}

// round 6
// speedup vs baseline: 1.6133x; 1.2350x over previous
#include <cuda_runtime.h>
#include <cuda_bf16.h>
#include <cstdint>

#define NN   256
#define CC   3
#define TT   300
#define VV   25
#define MM   2
#define DD   256
#define KK   5
#define TOPK 64
#define LTOT (NN*MM*TT)      // 153600
#define RPS  (MM*TT)         // 600
#define OUTS (CC*TOPK*VV*MM) // 9600
#define EPSV 1e-8f

// -------- scratch --------
__device__ float g_cls_sum[KK * DD];
__device__ float g_cnt[KK];
__device__ float g_cm[KK * DD];
__device__ float g_inter[KK];
__device__ float g_Sb;
__device__ float g_Sw;
__device__ float g_fs[LTOT];   // per-row frame score

// -------- kernel 0: zero --------
__global__ void k_zero() {
    int i = threadIdx.x;
    for (int j = i; j < KK * DD; j += 256) g_cls_sum[j] = 0.f;
    if (i < KK) g_cnt[i] = 0.f;
    if (i == 0) g_Sw = 0.f;
}

// -------- kernel 1: per-class sums + counts --------
// 600 blocks x 256 threads. Thread = (slice s = tid>>6 in 0..3, colgroup c = tid&63).
// Rows base+s+4*it, it=0..63. 8 loads staged per iteration for MLP.
__global__ void __launch_bounds__(256, 3) k_stats(const float4* __restrict__ xT4,
                                                  const int* __restrict__ labels) {
    __shared__ int    s_lbl[256];
    __shared__ float  s_cnt[KK];
    __shared__ float4 s_part[4][KK][64];   // 20 KB
    int tid = threadIdx.x;
    int c = tid & 63;
    int s = tid >> 6;
    int base = blockIdx.x * 256;
    if (tid < KK) s_cnt[tid] = 0.f;
    s_lbl[tid] = labels[base + tid];
    __syncthreads();
    atomicAdd(&s_cnt[s_lbl[tid]], 1.f);

    float4 a[KK];
#pragma unroll
    for (int k = 0; k < KK; k++) a[k] = make_float4(0.f, 0.f, 0.f, 0.f);

    const float4* p = xT4 + (size_t)(base + s) * 64 + c;
    for (int it = 0; it < 64; it += 8) {
        float4 v[8];
        int l[8];
#pragma unroll
        for (int u = 0; u < 8; u++) v[u] = __ldg(p + (size_t)(it + u) * 256);
#pragma unroll
        for (int u = 0; u < 8; u++) l[u] = s_lbl[(it + u) * 4 + s];
#pragma unroll
        for (int u = 0; u < 8; u++) {
            int lu = l[u];
            float4 vu = v[u];
            if      (lu == 0) { a[0].x += vu.x; a[0].y += vu.y; a[0].z += vu.z; a[0].w += vu.w; }
            else if (lu == 1) { a[1].x += vu.x; a[1].y += vu.y; a[1].z += vu.z; a[1].w += vu.w; }
            else if (lu == 2) { a[2].x += vu.x; a[2].y += vu.y; a[2].z += vu.z; a[2].w += vu.w; }
            else if (lu == 3) { a[3].x += vu.x; a[3].y += vu.y; a[3].z += vu.z; a[3].w += vu.w; }
            else              { a[4].x += vu.x; a[4].y += vu.y; a[4].z += vu.z; a[4].w += vu.w; }
        }
    }
#pragma unroll
    for (int k = 0; k < KK; k++) s_part[s][k][c] = a[k];
    __syncthreads();

    for (int idx = tid; idx < KK * 64; idx += 256) {
        int k = idx >> 6, cc = idx & 63;
        float4 s0 = s_part[0][k][cc], s1 = s_part[1][k][cc];
        float4 s2 = s_part[2][k][cc], s3 = s_part[3][k][cc];
        float4 t;
        t.x = (s0.x + s1.x) + (s2.x + s3.x);
        t.y = (s0.y + s1.y) + (s2.y + s3.y);
        t.z = (s0.z + s1.z) + (s2.z + s3.z);
        t.w = (s0.w + s1.w) + (s2.w + s3.w);
        atomicAdd(&g_cls_sum[k * DD + cc * 4 + 0], t.x);
        atomicAdd(&g_cls_sum[k * DD + cc * 4 + 1], t.y);
        atomicAdd(&g_cls_sum[k * DD + cc * 4 + 2], t.z);
        atomicAdd(&g_cls_sum[k * DD + cc * 4 + 3], t.w);
    }
    if (tid < KK) atomicAdd(&g_cnt[tid], s_cnt[tid]);
}

// -------- kernel 2: means, inter, Sb (1 block) --------
__global__ void __launch_bounds__(256) k_finalize() {
    __shared__ float s_cnt[KK];
    __shared__ float red[256];
    int d = threadIdx.x;
    if (d < KK) s_cnt[d] = g_cnt[d];
    __syncthreads();

    float om = 0.f;
    float cm[KK];
#pragma unroll
    for (int k = 0; k < KK; k++) {
        float s = g_cls_sum[k * DD + d];
        om += s;
        cm[k] = s / fmaxf(s_cnt[k], 1.f);
        g_cm[k * DD + d] = cm[k];
    }
    om *= (1.0f / (float)LTOT);

#pragma unroll
    for (int k = 0; k < KK; k++) {
        float diff = cm[k] - om;
        red[d] = diff * diff;
        __syncthreads();
        for (int s = 128; s > 0; s >>= 1) {
            if (d < s) red[d] += red[d + s];
            __syncthreads();
        }
        if (d == 0) g_inter[k] = red[0];
        __syncthreads();
    }
    if (d == 0) {
        float sb = 0.f;
#pragma unroll
        for (int k = 0; k < KK; k++) sb += s_cnt[k] * g_inter[k];
        g_Sb = sb;
    }
}

// -------- kernel 3: intra + frame scores -> g_fs, Sw --------
// 600 blocks x 256 threads = 8 warps; warp handles 32 rows, 4 rows per stage (8 LDG.128 in flight).
__global__ void __launch_bounds__(256) k_intra(const float4* __restrict__ xT4,
                                               const int* __restrict__ labels) {
    __shared__ float s_cm[KK * DD];   // 5 KB
    __shared__ float s_inter[KK];
    __shared__ int   s_lbl[256];
    __shared__ float s_fs[256];
    __shared__ float s_sw[8];

    int tid = threadIdx.x, lane = tid & 31, w = tid >> 5;
    int base = (600 - 1 - (int)blockIdx.x) * 256;   // reversed: L2-hot tail first

    for (int i = tid; i < KK * DD; i += 256) s_cm[i] = g_cm[i];
    if (tid < KK) s_inter[tid] = g_inter[tid];
    s_lbl[tid] = labels[base + tid];
    __syncthreads();

    const float4* cm4 = (const float4*)s_cm;
    float swacc = 0.f;
    int r0 = w * 32;

    for (int rr = 0; rr < 32; rr += 4) {
        int r = r0 + rr;
        float4 xv[8];
#pragma unroll
        for (int u = 0; u < 4; u++) {
            const float4* p = xT4 + (size_t)(base + r + u) * 64;
            xv[2 * u]     = __ldg(p + lane);
            xv[2 * u + 1] = __ldg(p + lane + 32);
        }
        float acc[4];
#pragma unroll
        for (int u = 0; u < 4; u++) {
            int lbl = s_lbl[r + u];
            const float4* m = cm4 + lbl * 64;
            float4 m0 = m[lane], m1 = m[lane + 32];
            float4 x0 = xv[2 * u], x1 = xv[2 * u + 1];
            float a = 0.f;
            float d0 = x0.x - m0.x; a = fmaf(d0, d0, a);
            float d1 = x0.y - m0.y; a = fmaf(d1, d1, a);
            float d2 = x0.z - m0.z; a = fmaf(d2, d2, a);
            float d3 = x0.w - m0.w; a = fmaf(d3, d3, a);
            float d4 = x1.x - m1.x; a = fmaf(d4, d4, a);
            float d5 = x1.y - m1.y; a = fmaf(d5, d5, a);
            float d6 = x1.z - m1.z; a = fmaf(d6, d6, a);
            float d7 = x1.w - m1.w; a = fmaf(d7, d7, a);
            acc[u] = a;
        }
#pragma unroll
        for (int u = 0; u < 4; u++) {
#pragma unroll
            for (int o = 16; o; o >>= 1) acc[u] += __shfl_xor_sync(0xFFFFFFFFu, acc[u], o);
        }
        if (lane == 0) {
#pragma unroll
            for (int u = 0; u < 4; u++) {
                swacc += acc[u];
                s_fs[r + u] = s_inter[s_lbl[r + u]] / (acc[u] + EPSV);
            }
        }
    }
    if (lane == 0) s_sw[w] = swacc;
    __syncthreads();
    if (tid == 0) {
        float s = 0.f;
#pragma unroll
        for (int i = 0; i < 8; i++) s += s_sw[i];
        atomicAdd(&g_Sw, s);
    }
    g_fs[base + tid] = s_fs[tid];   // coalesced
}

// -------- kernel 4: VF, topk, gather, loss --------
__global__ void __launch_bounds__(320) k_sel(const float* __restrict__ x,
                                             float* __restrict__ out) {
    __shared__ float s_v[TT];
    __shared__ int   s_flag[TT];
    __shared__ int   s_idx[TOPK];
    int n = blockIdx.x;
    int tid = threadIdx.x;

    if (n == 0 && tid == 0) out[0] = g_Sw / (g_Sb + EPSV);

    if (tid < TT)
        s_v[tid] = 0.5f * (g_fs[n * RPS + tid] + g_fs[n * RPS + TT + tid]);
    __syncthreads();

    if (tid < TT) {
        float mv = s_v[tid];
        int rank = 0;
        for (int j = 0; j < TT; j++) {
            float o = s_v[j];
            rank += (o > mv) || (o == mv && j < tid);
        }
        s_flag[tid] = (rank < TOPK) ? 1 : 0;
    }
    __syncthreads();
    if (tid < TT && s_flag[tid]) {
        int pos = 0;
        for (int j = 0; j < tid; j++) pos += s_flag[j];
        s_idx[pos] = tid;
    }
    __syncthreads();

    const float* xb = x + (size_t)n * CC * TT * (VV * MM);
    float* ob = out + 1 + (size_t)n * OUTS;
    for (int o = tid; o < OUTS; o += 320) {
        int cj = o / (VV * MM);
        int vm = o - cj * (VV * MM);
        int j = cj & 63;
        int c = cj >> 6;
        int t = s_idx[j];
        ob[o] = __ldg(xb + ((size_t)c * TT + t) * (VV * MM) + vm);
    }
}

extern "C" void kernel_launch(void* const* d_in, const int* in_sizes, int n_in,
                              void* d_out, int out_size) {
    const float*  x      = (const float*)d_in[0];
    const float4* xT4    = (const float4*)d_in[1];
    const int*    labels = (const int*)d_in[2];
    float* out = (float*)d_out;
    (void)in_sizes; (void)n_in; (void)out_size;

    k_zero<<<1, 256>>>();
    k_stats<<<LTOT / 256, 256>>>(xT4, labels);
    k_finalize<<<1, 256>>>();
    k_intra<<<LTOT / 256, 256>>>(xT4, labels);
    k_sel<<<NN, 320>>>(x, out);
}